// round 3
// baseline (speedup 1.0000x reference)
#include <cuda_runtime.h>
#include <cuda_fp16.h>
#include <cstdint>

#define BB 8
#define NQ 32
#define LQ 128
#define NK 16
#define LK 256
#define DD 128
#define KQ 64    // selected cand tokens per (b,q)
#define KK 128   // selected ctxt tokens per (b,k)
#define NEGV -99999.0f
#define PADD 136 // halfs per smem row (64B pad per 256B row -> conflict-free frag loads)

// Scratch (allocation-free rule: __device__ globals)
__device__ __align__(16) __half g_candSel[BB*NQ*KQ*DD];   // 4 MB
__device__ __align__(16) __half g_ctxtSel[BB*NK*KK*DD];   // 4 MB
__device__ int   g_candValid[BB*NQ];
__device__ float g_ctxtMask[BB*NK*KK];

__device__ __forceinline__ unsigned int fkey(float f) {
    unsigned int u = __float_as_uint(f);
    return (u & 0x80000000u) ? ~u : (u | 0x80000000u);  // monotone uint key
}

// Mask dtype sniffing: harness may store bool as 1-byte, int32, or float32.
// Returns 0 = 1-byte bool, 1 = int32, 2 = float32.
// Reference masks are all-ones: bytes -> 0x01010101, int32 -> 0x1, f32 -> 0x3F800000.
__device__ __forceinline__ int mask_mode(const unsigned char* m) {
    const unsigned int* w = (const unsigned int*)m;
    #pragma unroll
    for (int i = 0; i < 4; i++) {
        unsigned int v = w[i];
        if (v == 0x3F800000u) return 2;           // float 1.0
        if (v > 1u) return 0;                     // e.g. 0x01010101 packed bool bytes
    }
    return 1;                                     // int32 0/1
}
__device__ __forceinline__ bool read_mask(const unsigned char* m, int i, int mode) {
    if (mode == 0) return m[i] != 0;
    if (mode == 1) return ((const int*)m)[i] != 0;
    return ((const float*)m)[i] != 0.0f;
}

// ---------------------------------------------------------------------------
// Kernel 1: scores -> bitonic top-k -> gather to fp16 scratch
// blocks 0..255: cand rows (b,q), L=128,k=64 ; blocks 256..383: ctxt rows (b,k), L=256,k=128
// ---------------------------------------------------------------------------
__global__ __launch_bounds__(256) void select_gather_kernel(
    const float* __restrict__ cand, const float* __restrict__ ctxt,
    const unsigned char* __restrict__ mcand, const unsigned char* __restrict__ mctxt,
    const float* __restrict__ W, const float* __restrict__ bptr)
{
    __shared__ __align__(16) float Ws[DD];
    __shared__ unsigned long long keys[256];
    __shared__ int s_count;

    int tid = threadIdx.x;
    bool isCand = (blockIdx.x < BB*NQ);
    int row = isCand ? blockIdx.x : (blockIdx.x - BB*NQ);
    int L = isCand ? LQ : LK;
    int k = L >> 1;
    const float* rep = isCand ? (cand + (size_t)row * LQ * DD)
                              : (ctxt + (size_t)row * LK * DD);
    const unsigned char* mbase = isCand ? mcand : mctxt;
    int mmode = mask_mode(mbase);
    int moff  = row * L;

    if (tid < DD) Ws[tid] = W[tid];
    if (tid == 0) s_count = 0;
    __syncthreads();

    float bb = bptr[0];
    int wid = tid >> 5, lane = tid & 31;

    // scores: one warp per token
    for (int t = wid; t < L; t += 8) {
        float4 v  = ((const float4*)(rep + t * DD))[lane];
        float4 w4 = ((const float4*)Ws)[lane];
        float acc = v.x*w4.x + v.y*w4.y + v.z*w4.z + v.w*w4.w;
        #pragma unroll
        for (int off = 16; off; off >>= 1) acc += __shfl_xor_sync(0xffffffffu, acc, off);
        if (lane == 0) {
            float s = read_mask(mbase, moff + t, mmode) ? (acc + bb) : NEGV;
            keys[t] = ((unsigned long long)fkey(s) << 32) | (unsigned int)(~t);
        }
    }
    __syncthreads();

    // bitonic sort, descending (tie -> smaller index first via ~t in low bits)
    for (int size = 2; size <= L; size <<= 1) {
        for (int stride = size >> 1; stride > 0; stride >>= 1) {
            if (tid < L) {
                int j = tid ^ stride;
                if (j > tid) {
                    bool descend = ((tid & size) == 0);
                    unsigned long long a = keys[tid], c = keys[j];
                    if (descend ? (a < c) : (a > c)) { keys[tid] = c; keys[j] = a; }
                }
            }
            __syncthreads();
        }
    }

    if (isCand) {
        int cnt = 0;
        for (int j = tid; j < k; j += 256) {
            int t = (int)(~(unsigned int)keys[j]);
            if (read_mask(mbase, moff + t, mmode)) cnt++;
        }
        if (cnt) atomicAdd(&s_count, cnt);
        __syncthreads();
        if (tid == 0) g_candValid[row] = s_count;
        __half* dst = g_candSel + (size_t)row * KQ * DD;
        for (int e = tid; e < KQ * DD; e += 256) {
            int j = e >> 7, d = e & 127;
            int t = (int)(~(unsigned int)keys[j]);
            dst[e] = __float2half_rn(rep[t * DD + d]);
        }
    } else {
        for (int j = tid; j < k; j += 256) {
            int t = (int)(~(unsigned int)keys[j]);
            g_ctxtMask[row * KK + j] = read_mask(mbase, moff + t, mmode) ? 1.0f : 0.0f;
        }
        __half* dst = g_ctxtSel + (size_t)row * KK * DD;
        for (int e = tid; e < KK * DD; e += 256) {
            int j = e >> 7, d = e & 127;
            int t = (int)(~(unsigned int)keys[j]);
            dst[e] = __float2half_rn(rep[t * DD + d]);
        }
    }
}

// ---------------------------------------------------------------------------
// Kernel 2: per (b,q): S = A(64x128) . ctxt^T, colmax over valid cand rows,
// masked mean per k. mma.sync m16n8k16 f16->f32.
// warp grid: 4(m) x 2(n) over a 64x64 chunk; A-frags register-resident.
// ---------------------------------------------------------------------------
__device__ __forceinline__ void atomicMaxF(float* addr, float v) {
    if (v >= 0.f) atomicMax((int*)addr, __float_as_int(v));
    else          atomicMin((unsigned int*)addr, __float_as_uint(v));
}

__global__ __launch_bounds__(256) void gemm_max_mean_kernel(float* __restrict__ out)
{
    __shared__ __align__(16) __half Bs[64 * PADD];  // 17.4 KB; also stages A once
    __shared__ float colmax[64];
    __shared__ float sAccV, sAccM;

    int tid  = threadIdx.x;
    int lane = tid & 31, wid = tid >> 5;
    int wm = wid >> 1;            // 0..3 : rows [wm*16, +16)
    int wn = wid & 1;             // 0..1 : cols [wn*32, +32)
    int bq = blockIdx.x;
    int b  = bq >> 5;             // NQ = 32
    int g  = lane >> 2;           // 0..7
    int cpair = (lane & 3) * 2;

    // Stage A (64x128 halfs) into smem, coalesced
    {
        const __half* Ag = g_candSel + (size_t)bq * KQ * DD;
        for (int i = tid; i < 64 * 16; i += 256) {
            int r = i >> 4, seg = i & 15;
            *(int4*)&Bs[r * PADD + seg * 8] = *(const int4*)&Ag[r * DD + seg * 8];
        }
    }
    __syncthreads();

    // A fragments for this warp's 16 rows, all 8 k-steps (register resident)
    unsigned int aF[8][4];
    {
        int r0 = wm * 16 + g;
        #pragma unroll
        for (int ks = 0; ks < 8; ks++) {
            int base = r0 * PADD + ks * 16 + cpair;
            aF[ks][0] = *(const unsigned int*)&Bs[base];
            aF[ks][1] = *(const unsigned int*)&Bs[base + 8 * PADD];
            aF[ks][2] = *(const unsigned int*)&Bs[base + 8];
            aF[ks][3] = *(const unsigned int*)&Bs[base + 8 * PADD + 8];
        }
    }
    int nvalid = g_candValid[bq];
    __syncthreads();  // done with A staging buffer

    for (int kk = 0; kk < NK; kk++) {
        if (tid == 0) { sAccV = 0.f; sAccM = 0.f; }
        #pragma unroll 1
        for (int h = 0; h < 2; h++) {
            __syncthreads();  // prior chunk consumers done; sAcc zero visible
            // load 64 ctxt tokens x 128 dims
            const __half* Bg = g_ctxtSel + (((size_t)(b * NK + kk)) * KK + h * 64) * DD;
            for (int i = tid; i < 64 * 16; i += 256) {
                int r = i >> 4, seg = i & 15;
                *(int4*)&Bs[r * PADD + seg * 8] = *(const int4*)&Bg[r * DD + seg * 8];
            }
            if (tid < 64) colmax[tid] = NEGV;
            __syncthreads();

            float C[4][4];
            #pragma unroll
            for (int ni = 0; ni < 4; ni++)
                #pragma unroll
                for (int j = 0; j < 4; j++) C[ni][j] = 0.f;

            #pragma unroll
            for (int ks = 0; ks < 8; ks++) {
                unsigned int bF[4][2];
                #pragma unroll
                for (int ni = 0; ni < 4; ni++) {
                    int n = wn * 32 + ni * 8 + g;           // ctxt token in chunk
                    int base = n * PADD + ks * 16 + cpair;  // [e][d] layout
                    bF[ni][0] = *(const unsigned int*)&Bs[base];
                    bF[ni][1] = *(const unsigned int*)&Bs[base + 8];
                }
                #pragma unroll
                for (int ni = 0; ni < 4; ni++) {
                    asm volatile(
                        "mma.sync.aligned.m16n8k16.row.col.f32.f16.f16.f32 "
                        "{%0,%1,%2,%3}, {%4,%5,%6,%7}, {%8,%9}, {%0,%1,%2,%3};\n"
                        : "+f"(C[ni][0]), "+f"(C[ni][1]), "+f"(C[ni][2]), "+f"(C[ni][3])
                        : "r"(aF[ks][0]), "r"(aF[ks][1]), "r"(aF[ks][2]), "r"(aF[ks][3]),
                          "r"(bF[ni][0]), "r"(bF[ni][1]));
                }
            }

            // masked column max (rows >= nvalid excluded)
            int r0 = wm * 16 + g, r1 = r0 + 8;
            bool ok0 = (r0 < nvalid), ok1 = (r1 < nvalid);
            #pragma unroll
            for (int ni = 0; ni < 4; ni++) {
                float m0 = fmaxf(ok0 ? C[ni][0] : NEGV, ok1 ? C[ni][2] : NEGV);
                float m1 = fmaxf(ok0 ? C[ni][1] : NEGV, ok1 ? C[ni][3] : NEGV);
                #pragma unroll
                for (int off = 4; off < 32; off <<= 1) {
                    m0 = fmaxf(m0, __shfl_xor_sync(0xffffffffu, m0, off));
                    m1 = fmaxf(m1, __shfl_xor_sync(0xffffffffu, m1, off));
                }
                if (lane < 4) {
                    int col = wn * 32 + ni * 8 + cpair;
                    atomicMaxF(&colmax[col],     m0);
                    atomicMaxF(&colmax[col + 1], m1);
                }
            }
            __syncthreads();

            // masked mean accumulation over this 64-token chunk
            if (tid < 64) {
                float m = g_ctxtMask[(b * NK + kk) * KK + h * 64 + tid];
                float v = colmax[tid] * m;
                #pragma unroll
                for (int off = 16; off; off >>= 1) {
                    v += __shfl_xor_sync(0xffffffffu, v, off);
                    m += __shfl_xor_sync(0xffffffffu, m, off);
                }
                if (lane == 0) { atomicAdd(&sAccV, v); atomicAdd(&sAccM, m); }
            }
        }
        __syncthreads();
        if (tid == 0) out[bq * NK + kk] = sAccV / sAccM;
    }
}

// ---------------------------------------------------------------------------
extern "C" void kernel_launch(void* const* d_in, const int* in_sizes, int n_in,
                              void* d_out, int out_size)
{
    const float*         cand  = (const float*)d_in[0];          // [8,32,128,128]
    const float*         ctxt  = (const float*)d_in[1];          // [8,16,256,128]
    const unsigned char* mcand = (const unsigned char*)d_in[2];  // [8,32,128] bool (dtype sniffed)
    const unsigned char* mctxt = (const unsigned char*)d_in[3];  // [8,16,256] bool (dtype sniffed)
    const float*         W     = (const float*)d_in[4];          // [128]
    const float*         bptr  = (const float*)d_in[5];          // [1]
    float* out = (float*)d_out;                                  // [8,32,16]

    select_gather_kernel<<<BB*NQ + BB*NK, 256>>>(cand, ctxt, mcand, mctxt, W, bptr);
    gemm_max_mean_kernel<<<BB*NQ, 256>>>(out);
}

// round 4
// speedup vs baseline: 1.4270x; 1.4270x over previous
#include <cuda_runtime.h>
#include <cuda_fp16.h>
#include <cstdint>

#define BB 8
#define NQ 32
#define LQ 128
#define NK 16
#define LK 256
#define DD 128
#define KQ 64    // selected cand tokens per (b,q)
#define KK 128   // selected ctxt tokens per (b,k)
#define NEGV -99999.0f
#define PADD 136 // halfs per smem row (16B pad per 256B row -> conflict-free frag loads)

// Dynamic smem layout for K2: A[64*PADD] halfs, B[128*PADD] halfs, colmax[128] floats
#define SMEM_K2 ((64 + 128) * PADD * 2 + 128 * 4)

// Scratch (allocation-free rule: __device__ globals)
__device__ __align__(16) __half g_candSel[BB*NQ*KQ*DD];   // 4 MB
__device__ __align__(16) __half g_ctxtSel[BB*NK*KK*DD];   // 4 MB
__device__ int   g_candValid[BB*NQ];
__device__ float g_ctxtMask[BB*NK*KK];

__device__ __forceinline__ unsigned int fkey(float f) {
    unsigned int u = __float_as_uint(f);
    return (u & 0x80000000u) ? ~u : (u | 0x80000000u);  // monotone uint key
}

// Mask dtype sniffing (confirmed int32 on this harness, keep robust anyway).
// 0 = 1-byte bool, 1 = int32, 2 = float32
__device__ __forceinline__ int mask_mode(const unsigned char* m) {
    const unsigned int* w = (const unsigned int*)m;
    #pragma unroll
    for (int i = 0; i < 4; i++) {
        unsigned int v = w[i];
        if (v == 0x3F800000u) return 2;
        if (v > 1u) return 0;
    }
    return 1;
}
__device__ __forceinline__ bool read_mask(const unsigned char* m, int i, int mode) {
    if (mode == 0) return m[i] != 0;
    if (mode == 1) return ((const int*)m)[i] != 0;
    return ((const float*)m)[i] != 0.0f;
}

// ---------------------------------------------------------------------------
// Kernel 1: scores -> bitonic top-k -> gather to fp16 scratch
// blocks 0..255: cand rows (b,q), L=128,k=64 ; blocks 256..383: ctxt rows (b,k), L=256,k=128
// ---------------------------------------------------------------------------
__global__ __launch_bounds__(256) void select_gather_kernel(
    const float* __restrict__ cand, const float* __restrict__ ctxt,
    const unsigned char* __restrict__ mcand, const unsigned char* __restrict__ mctxt,
    const float* __restrict__ W, const float* __restrict__ bptr)
{
    __shared__ __align__(16) float Ws[DD];
    __shared__ unsigned long long keys[256];
    __shared__ int s_count;

    int tid = threadIdx.x;
    bool isCand = (blockIdx.x < BB*NQ);
    int row = isCand ? blockIdx.x : (blockIdx.x - BB*NQ);
    int L = isCand ? LQ : LK;
    int k = L >> 1;
    const float* rep = isCand ? (cand + (size_t)row * LQ * DD)
                              : (ctxt + (size_t)row * LK * DD);
    const unsigned char* mbase = isCand ? mcand : mctxt;
    int mmode = mask_mode(mbase);
    int moff  = row * L;

    if (tid < DD) Ws[tid] = W[tid];
    if (tid == 0) s_count = 0;
    __syncthreads();

    float bb = bptr[0];
    int wid = tid >> 5, lane = tid & 31;

    for (int t = wid; t < L; t += 8) {
        float4 v  = ((const float4*)(rep + t * DD))[lane];
        float4 w4 = ((const float4*)Ws)[lane];
        float acc = v.x*w4.x + v.y*w4.y + v.z*w4.z + v.w*w4.w;
        #pragma unroll
        for (int off = 16; off; off >>= 1) acc += __shfl_xor_sync(0xffffffffu, acc, off);
        if (lane == 0) {
            float s = read_mask(mbase, moff + t, mmode) ? (acc + bb) : NEGV;
            keys[t] = ((unsigned long long)fkey(s) << 32) | (unsigned int)(~t);
        }
    }
    __syncthreads();

    // bitonic sort, descending
    for (int size = 2; size <= L; size <<= 1) {
        for (int stride = size >> 1; stride > 0; stride >>= 1) {
            if (tid < L) {
                int j = tid ^ stride;
                if (j > tid) {
                    bool descend = ((tid & size) == 0);
                    unsigned long long a = keys[tid], c = keys[j];
                    if (descend ? (a < c) : (a > c)) { keys[tid] = c; keys[j] = a; }
                }
            }
            __syncthreads();
        }
    }

    if (isCand) {
        int cnt = 0;
        for (int j = tid; j < k; j += 256) {
            int t = (int)(~(unsigned int)keys[j]);
            if (read_mask(mbase, moff + t, mmode)) cnt++;
        }
        if (cnt) atomicAdd(&s_count, cnt);
        __syncthreads();
        if (tid == 0) g_candValid[row] = s_count;
        __half* dst = g_candSel + (size_t)row * KQ * DD;
        for (int e = tid; e < KQ * DD; e += 256) {
            int j = e >> 7, d = e & 127;
            int t = (int)(~(unsigned int)keys[j]);
            dst[e] = __float2half_rn(rep[t * DD + d]);
        }
    } else {
        for (int j = tid; j < k; j += 256) {
            int t = (int)(~(unsigned int)keys[j]);
            g_ctxtMask[row * KK + j] = read_mask(mbase, moff + t, mmode) ? 1.0f : 0.0f;
        }
        __half* dst = g_ctxtSel + (size_t)row * KK * DD;
        for (int e = tid; e < KK * DD; e += 256) {
            int j = e >> 7, d = e & 127;
            int t = (int)(~(unsigned int)keys[j]);
            dst[e] = __float2half_rn(rep[t * DD + d]);
        }
    }
}

// ---------------------------------------------------------------------------
// Kernel 2: one block per (bq, kk). S = A(64x128) . B(128x128)^T, colmax over
// valid cand rows, masked mean -> out[bq*NK+kk]. 3 barriers total per block.
// warps: wm=wid>>1 (4) x wn=wid&1 (2); warp tile 16 rows x 64 cols (8 n8 tiles)
// ---------------------------------------------------------------------------
__device__ __forceinline__ void atomicMaxF(float* addr, float v) {
    if (v >= 0.f) atomicMax((int*)addr, __float_as_int(v));
    else          atomicMin((unsigned int*)addr, __float_as_uint(v));
}

__global__ __launch_bounds__(256) void gemm_max_mean_kernel(float* __restrict__ out)
{
    extern __shared__ __align__(16) unsigned char smraw[];
    __half* As  = (__half*)smraw;                       // 64 x PADD
    __half* Bsh = (__half*)smraw + 64 * PADD;           // 128 x PADD
    float*  colmax = (float*)((__half*)smraw + (64 + 128) * PADD);  // 128
    __shared__ float sAccV, sAccM;

    int tid  = threadIdx.x;
    int lane = tid & 31, wid = tid >> 5;
    int wm = wid >> 1;            // 0..3 : rows [wm*16, +16)
    int wn = wid & 1;             // 0..1 : cols [wn*64, +64)
    int blk = blockIdx.x;
    int bq = blk >> 4;            // NK = 16
    int kk = blk & 15;
    int b  = bq >> 5;             // NQ = 32
    int g  = lane >> 2;           // 0..7
    int cpair = (lane & 3) * 2;

    // Stage A (64x128) and B (128x128) halfs into smem, coalesced int4
    {
        const __half* Ag = g_candSel + (size_t)bq * KQ * DD;
        for (int i = tid; i < 64 * 16; i += 256) {
            int r = i >> 4, seg = i & 15;
            *(int4*)&As[r * PADD + seg * 8] = *(const int4*)&Ag[r * DD + seg * 8];
        }
        const __half* Bg = g_ctxtSel + ((size_t)(b * NK + kk)) * KK * DD;
        for (int i = tid; i < 128 * 16; i += 256) {
            int r = i >> 4, seg = i & 15;
            *(int4*)&Bsh[r * PADD + seg * 8] = *(const int4*)&Bg[r * DD + seg * 8];
        }
    }
    if (tid < 128) colmax[tid] = NEGV;
    if (tid == 0) { sAccV = 0.f; sAccM = 0.f; }
    int nvalid = g_candValid[bq];
    __syncthreads();

    float C[8][4];
    #pragma unroll
    for (int ni = 0; ni < 8; ni++)
        #pragma unroll
        for (int j = 0; j < 4; j++) C[ni][j] = 0.f;

    int r0 = wm * 16 + g;
    #pragma unroll
    for (int ks = 0; ks < 8; ks++) {
        unsigned int aF[4];
        {
            int base = r0 * PADD + ks * 16 + cpair;
            aF[0] = *(const unsigned int*)&As[base];
            aF[1] = *(const unsigned int*)&As[base + 8 * PADD];
            aF[2] = *(const unsigned int*)&As[base + 8];
            aF[3] = *(const unsigned int*)&As[base + 8 * PADD + 8];
        }
        #pragma unroll
        for (int ni = 0; ni < 8; ni++) {
            int n = wn * 64 + ni * 8 + g;           // ctxt token (0..127)
            int base = n * PADD + ks * 16 + cpair;
            unsigned int b0 = *(const unsigned int*)&Bsh[base];
            unsigned int b1 = *(const unsigned int*)&Bsh[base + 8];
            asm volatile(
                "mma.sync.aligned.m16n8k16.row.col.f32.f16.f16.f32 "
                "{%0,%1,%2,%3}, {%4,%5,%6,%7}, {%8,%9}, {%0,%1,%2,%3};\n"
                : "+f"(C[ni][0]), "+f"(C[ni][1]), "+f"(C[ni][2]), "+f"(C[ni][3])
                : "r"(aF[0]), "r"(aF[1]), "r"(aF[2]), "r"(aF[3]),
                  "r"(b0), "r"(b1));
        }
    }

    // masked column max (rows >= nvalid excluded)
    bool ok0 = (r0 < nvalid), ok1 = (r0 + 8 < nvalid);
    #pragma unroll
    for (int ni = 0; ni < 8; ni++) {
        float m0 = fmaxf(ok0 ? C[ni][0] : NEGV, ok1 ? C[ni][2] : NEGV);
        float m1 = fmaxf(ok0 ? C[ni][1] : NEGV, ok1 ? C[ni][3] : NEGV);
        #pragma unroll
        for (int off = 4; off < 32; off <<= 1) {
            m0 = fmaxf(m0, __shfl_xor_sync(0xffffffffu, m0, off));
            m1 = fmaxf(m1, __shfl_xor_sync(0xffffffffu, m1, off));
        }
        if (lane < 4) {
            int col = wn * 64 + ni * 8 + cpair;
            atomicMaxF(&colmax[col],     m0);
            atomicMaxF(&colmax[col + 1], m1);
        }
    }
    __syncthreads();

    // masked mean over 128 ctxt tokens
    if (tid < 128) {
        float m = g_ctxtMask[(b * NK + kk) * KK + tid];
        float v = colmax[tid] * m;
        #pragma unroll
        for (int off = 16; off; off >>= 1) {
            v += __shfl_xor_sync(0xffffffffu, v, off);
            m += __shfl_xor_sync(0xffffffffu, m, off);
        }
        if (lane == 0) { atomicAdd(&sAccV, v); atomicAdd(&sAccM, m); }
    }
    __syncthreads();
    if (tid == 0) out[bq * NK + kk] = sAccV / sAccM;
}

// ---------------------------------------------------------------------------
extern "C" void kernel_launch(void* const* d_in, const int* in_sizes, int n_in,
                              void* d_out, int out_size)
{
    const float*         cand  = (const float*)d_in[0];          // [8,32,128,128]
    const float*         ctxt  = (const float*)d_in[1];          // [8,16,256,128]
    const unsigned char* mcand = (const unsigned char*)d_in[2];  // [8,32,128] (dtype sniffed)
    const unsigned char* mctxt = (const unsigned char*)d_in[3];  // [8,16,256] (dtype sniffed)
    const float*         W     = (const float*)d_in[4];          // [128]
    const float*         bptr  = (const float*)d_in[5];          // [1]
    float* out = (float*)d_out;                                  // [8,32,16]

    cudaFuncSetAttribute(gemm_max_mean_kernel,
                         cudaFuncAttributeMaxDynamicSharedMemorySize, SMEM_K2);

    select_gather_kernel<<<BB*NQ + BB*NK, 256>>>(cand, ctxt, mcand, mctxt, W, bptr);
    gemm_max_mean_kernel<<<BB*NQ*NK, 256, SMEM_K2>>>(out);
}

// round 5
// speedup vs baseline: 1.4582x; 1.0219x over previous
#include <cuda_runtime.h>
#include <cuda_fp16.h>
#include <cstdint>

#define BB 8
#define NQ 32
#define LQ 128
#define NK 16
#define LK 256
#define DD 128
#define KQ 64    // selected cand tokens per (b,q)
#define KK 128   // selected ctxt tokens per (b,k)
#define NEGV -99999.0f
#define PADD 136 // halfs per smem row (16B pad per 256B row -> conflict-free ldmatrix)

// Dynamic smem for K2: A[64*PADD] + B[128*PADD] halfs, colmax[128] floats
#define SMEM_K2 ((64 + 128) * PADD * 2 + 128 * 4)

// Scratch (allocation-free rule: __device__ globals)
__device__ __align__(16) __half g_candSel[BB*NQ*KQ*DD];   // 4 MB
__device__ __align__(16) __half g_ctxtSel[BB*NK*KK*DD];   // 4 MB
__device__ int   g_candValid[BB*NQ];
__device__ float g_ctxtMask[BB*NK*KK];

__device__ __forceinline__ unsigned int fkey(float f) {
    unsigned int u = __float_as_uint(f);
    return (u & 0x80000000u) ? ~u : (u | 0x80000000u);  // monotone uint key
}

// Mask dtype sniffing (confirmed int32 on this harness; keep robust).
__device__ __forceinline__ int mask_mode(const unsigned char* m) {
    const unsigned int* w = (const unsigned int*)m;
    #pragma unroll
    for (int i = 0; i < 4; i++) {
        unsigned int v = w[i];
        if (v == 0x3F800000u) return 2;
        if (v > 1u) return 0;
    }
    return 1;
}
__device__ __forceinline__ bool read_mask(const unsigned char* m, int i, int mode) {
    if (mode == 0) return m[i] != 0;
    if (mode == 1) return ((const int*)m)[i] != 0;
    return ((const float*)m)[i] != 0.0f;
}

// ---------------------------------------------------------------------------
// Kernel 1: scores -> bitonic top-k -> gather to fp16 scratch
// ---------------------------------------------------------------------------
__global__ __launch_bounds__(256) void select_gather_kernel(
    const float* __restrict__ cand, const float* __restrict__ ctxt,
    const unsigned char* __restrict__ mcand, const unsigned char* __restrict__ mctxt,
    const float* __restrict__ W, const float* __restrict__ bptr)
{
    __shared__ __align__(16) float Ws[DD];
    __shared__ unsigned long long keys[256];
    __shared__ int s_count;

    int tid = threadIdx.x;
    bool isCand = (blockIdx.x < BB*NQ);
    int row = isCand ? blockIdx.x : (blockIdx.x - BB*NQ);
    int L = isCand ? LQ : LK;
    int k = L >> 1;
    const float* rep = isCand ? (cand + (size_t)row * LQ * DD)
                              : (ctxt + (size_t)row * LK * DD);
    const unsigned char* mbase = isCand ? mcand : mctxt;
    int mmode = mask_mode(mbase);
    int moff  = row * L;

    if (tid < DD) Ws[tid] = W[tid];
    if (tid == 0) s_count = 0;
    __syncthreads();

    float bb = bptr[0];
    int wid = tid >> 5, lane = tid & 31;

    for (int t = wid; t < L; t += 8) {
        float4 v  = ((const float4*)(rep + t * DD))[lane];
        float4 w4 = ((const float4*)Ws)[lane];
        float acc = v.x*w4.x + v.y*w4.y + v.z*w4.z + v.w*w4.w;
        #pragma unroll
        for (int off = 16; off; off >>= 1) acc += __shfl_xor_sync(0xffffffffu, acc, off);
        if (lane == 0) {
            float s = read_mask(mbase, moff + t, mmode) ? (acc + bb) : NEGV;
            keys[t] = ((unsigned long long)fkey(s) << 32) | (unsigned int)(~t);
        }
    }
    __syncthreads();

    // bitonic sort, descending
    for (int size = 2; size <= L; size <<= 1) {
        for (int stride = size >> 1; stride > 0; stride >>= 1) {
            if (tid < L) {
                int j = tid ^ stride;
                if (j > tid) {
                    bool descend = ((tid & size) == 0);
                    unsigned long long a = keys[tid], c = keys[j];
                    if (descend ? (a < c) : (a > c)) { keys[tid] = c; keys[j] = a; }
                }
            }
            __syncthreads();
        }
    }

    if (isCand) {
        int cnt = 0;
        for (int j = tid; j < k; j += 256) {
            int t = (int)(~(unsigned int)keys[j]);
            if (read_mask(mbase, moff + t, mmode)) cnt++;
        }
        if (cnt) atomicAdd(&s_count, cnt);
        __syncthreads();
        if (tid == 0) g_candValid[row] = s_count;
        __half2* dst = (__half2*)(g_candSel + (size_t)row * KQ * DD);
        for (int e = tid; e < KQ * (DD/2); e += 256) {
            int j = e >> 6, d = e & 63;
            int t = (int)(~(unsigned int)keys[j]);
            float2 v = ((const float2*)(rep + t * DD))[d];
            dst[e] = __floats2half2_rn(v.x, v.y);
        }
    } else {
        for (int j = tid; j < k; j += 256) {
            int t = (int)(~(unsigned int)keys[j]);
            g_ctxtMask[row * KK + j] = read_mask(mbase, moff + t, mmode) ? 1.0f : 0.0f;
        }
        __half2* dst = (__half2*)(g_ctxtSel + (size_t)row * KK * DD);
        for (int e = tid; e < KK * (DD/2); e += 256) {
            int j = e >> 6, d = e & 63;
            int t = (int)(~(unsigned int)keys[j]);
            float2 v = ((const float2*)(rep + t * DD))[d];
            dst[e] = __floats2half2_rn(v.x, v.y);
        }
    }
}

// ---------------------------------------------------------------------------
// Kernel 2: one block per (bq, kk). ldmatrix-fed m16n8k16 GEMM + colmax + mean
// ---------------------------------------------------------------------------
__device__ __forceinline__ void atomicMaxF(float* addr, float v) {
    if (v >= 0.f) atomicMax((int*)addr, __float_as_int(v));
    else          atomicMin((unsigned int*)addr, __float_as_uint(v));
}

__device__ __forceinline__ void ldsm_x4(unsigned int& r0, unsigned int& r1,
                                        unsigned int& r2, unsigned int& r3,
                                        unsigned int saddr) {
    asm volatile("ldmatrix.sync.aligned.m8n8.x4.shared.b16 {%0,%1,%2,%3}, [%4];"
                 : "=r"(r0), "=r"(r1), "=r"(r2), "=r"(r3) : "r"(saddr));
}

__global__ __launch_bounds__(256) void gemm_max_mean_kernel(float* __restrict__ out)
{
    extern __shared__ __align__(16) unsigned char smraw[];
    __half* As  = (__half*)smraw;                       // 64 x PADD
    __half* Bsh = (__half*)smraw + 64 * PADD;           // 128 x PADD
    float*  colmax = (float*)((__half*)smraw + (64 + 128) * PADD);  // 128
    __shared__ float sAccV, sAccM;

    int tid  = threadIdx.x;
    int lane = tid & 31, wid = tid >> 5;
    int wm = wid >> 1;            // 0..3 : rows [wm*16, +16)
    int wn = wid & 1;             // 0..1 : cols [wn*64, +64)
    int blk = blockIdx.x;
    int bq = blk >> 4;            // NK = 16
    int kk = blk & 15;
    int b  = bq >> 5;             // NQ = 32
    int g  = lane >> 2;
    int cpair = (lane & 3) * 2;

    // Stage A (64x128) and B (128x128) into padded smem
    {
        const __half* Ag = g_candSel + (size_t)bq * KQ * DD;
        for (int i = tid; i < 64 * 16; i += 256) {
            int r = i >> 4, seg = i & 15;
            *(int4*)&As[r * PADD + seg * 8] = *(const int4*)&Ag[r * DD + seg * 8];
        }
        const __half* Bg = g_ctxtSel + ((size_t)(b * NK + kk)) * KK * DD;
        for (int i = tid; i < 128 * 16; i += 256) {
            int r = i >> 4, seg = i & 15;
            *(int4*)&Bsh[r * PADD + seg * 8] = *(const int4*)&Bg[r * DD + seg * 8];
        }
    }
    if (tid < 128) colmax[tid] = NEGV;
    if (tid == 0) { sAccV = 0.f; sAccM = 0.f; }
    int nvalid = g_candValid[bq];
    __syncthreads();

    // ldmatrix lane addressing: tile t = lane>>3, row-in-tile = lane&7
    int t8   = lane >> 3;         // 0..3
    int rsub = lane & 7;
    // A 16x16 patch at (wm*16, ks*16): tiles (row t&1, col t>>1)
    unsigned int aAddr = (unsigned int)__cvta_generic_to_shared(
        &As[(wm * 16 + (t8 & 1) * 8 + rsub) * PADD + (t8 >> 1) * 8]);
    // B 16(n)x16(k) patches at (wn*64 + p*16, ks*16)
    unsigned int bAddr0 = (unsigned int)__cvta_generic_to_shared(
        &Bsh[(wn * 64 + (t8 & 1) * 8 + rsub) * PADD + (t8 >> 1) * 8]);

    float C[8][4];
    #pragma unroll
    for (int ni = 0; ni < 8; ni++)
        #pragma unroll
        for (int j = 0; j < 4; j++) C[ni][j] = 0.f;

    #pragma unroll
    for (int ks = 0; ks < 8; ks++) {
        unsigned int a0, a1, a2, a3;
        ldsm_x4(a0, a1, a2, a3, aAddr + ks * 32);
        #pragma unroll
        for (int p = 0; p < 4; p++) {
            unsigned int q0, q1, q2, q3;
            ldsm_x4(q0, q1, q2, q3, bAddr0 + p * (16 * PADD * 2) + ks * 32);
            // n-frag 2p   : b0=q0, b1=q2 ; n-frag 2p+1 : b0=q1, b1=q3
            asm volatile(
                "mma.sync.aligned.m16n8k16.row.col.f32.f16.f16.f32 "
                "{%0,%1,%2,%3}, {%4,%5,%6,%7}, {%8,%9}, {%0,%1,%2,%3};\n"
                : "+f"(C[2*p][0]), "+f"(C[2*p][1]), "+f"(C[2*p][2]), "+f"(C[2*p][3])
                : "r"(a0), "r"(a1), "r"(a2), "r"(a3), "r"(q0), "r"(q2));
            asm volatile(
                "mma.sync.aligned.m16n8k16.row.col.f32.f16.f16.f32 "
                "{%0,%1,%2,%3}, {%4,%5,%6,%7}, {%8,%9}, {%0,%1,%2,%3};\n"
                : "+f"(C[2*p+1][0]), "+f"(C[2*p+1][1]), "+f"(C[2*p+1][2]), "+f"(C[2*p+1][3])
                : "r"(a0), "r"(a1), "r"(a2), "r"(a3), "r"(q1), "r"(q3));
        }
    }

    // masked column max (rows >= nvalid excluded)
    int r0 = wm * 16 + g;
    bool ok0 = (r0 < nvalid), ok1 = (r0 + 8 < nvalid);
    #pragma unroll
    for (int ni = 0; ni < 8; ni++) {
        float m0 = fmaxf(ok0 ? C[ni][0] : NEGV, ok1 ? C[ni][2] : NEGV);
        float m1 = fmaxf(ok0 ? C[ni][1] : NEGV, ok1 ? C[ni][3] : NEGV);
        #pragma unroll
        for (int off = 4; off < 32; off <<= 1) {
            m0 = fmaxf(m0, __shfl_xor_sync(0xffffffffu, m0, off));
            m1 = fmaxf(m1, __shfl_xor_sync(0xffffffffu, m1, off));
        }
        if (lane < 4) {
            int col = wn * 64 + ni * 8 + cpair;
            atomicMaxF(&colmax[col],     m0);
            atomicMaxF(&colmax[col + 1], m1);
        }
    }
    __syncthreads();

    // masked mean over 128 ctxt tokens
    if (tid < 128) {
        float m = g_ctxtMask[(b * NK + kk) * KK + tid];
        float v = colmax[tid] * m;
        #pragma unroll
        for (int off = 16; off; off >>= 1) {
            v += __shfl_xor_sync(0xffffffffu, v, off);
            m += __shfl_xor_sync(0xffffffffu, m, off);
        }
        if (lane == 0) { atomicAdd(&sAccV, v); atomicAdd(&sAccM, m); }
    }
    __syncthreads();
    if (tid == 0) out[bq * NK + kk] = sAccV / sAccM;
}

// ---------------------------------------------------------------------------
extern "C" void kernel_launch(void* const* d_in, const int* in_sizes, int n_in,
                              void* d_out, int out_size)
{
    const float*         cand  = (const float*)d_in[0];          // [8,32,128,128]
    const float*         ctxt  = (const float*)d_in[1];          // [8,16,256,128]
    const unsigned char* mcand = (const unsigned char*)d_in[2];  // [8,32,128] (dtype sniffed)
    const unsigned char* mctxt = (const unsigned char*)d_in[3];  // [8,16,256] (dtype sniffed)
    const float*         W     = (const float*)d_in[4];          // [128]
    const float*         bptr  = (const float*)d_in[5];          // [1]
    float* out = (float*)d_out;                                  // [8,32,16]

    cudaFuncSetAttribute(gemm_max_mean_kernel,
                         cudaFuncAttributeMaxDynamicSharedMemorySize, SMEM_K2);

    select_gather_kernel<<<BB*NQ + BB*NK, 256>>>(cand, ctxt, mcand, mctxt, W, bptr);
    gemm_max_mean_kernel<<<BB*NQ*NK, 256, SMEM_K2>>>(out);
}

// round 6
// speedup vs baseline: 1.6563x; 1.1358x over previous
#include <cuda_runtime.h>
#include <cuda_fp16.h>
#include <cstdint>

#define BB 8
#define NQ 32
#define LQ 128
#define NK 16
#define LK 256
#define DD 128
#define KQ 64
#define KK 128
#define NEGV -99999.0f
#define PADD 136 // halfs per smem row (16B pad per 256B row -> conflict-free ldmatrix)

#define SMEM_K2 ((64 + 128) * PADD * 2 + 128 * 4)

__device__ __align__(16) __half g_candSel[BB*NQ*KQ*DD];   // 4 MB
__device__ __align__(16) __half g_ctxtSel[BB*NK*KK*DD];   // 4 MB
__device__ int   g_candValid[BB*NQ];
__device__ float g_ctxtMask[BB*NK*KK];

__device__ __forceinline__ unsigned int fkey(float f) {
    unsigned int u = __float_as_uint(f);
    return (u & 0x80000000u) ? ~u : (u | 0x80000000u);
}

// Mask dtype sniffing (confirmed int32 on this harness; keep robust).
__device__ __forceinline__ int mask_mode(const unsigned char* m) {
    const unsigned int* w = (const unsigned int*)m;
    #pragma unroll
    for (int i = 0; i < 4; i++) {
        unsigned int v = w[i];
        if (v == 0x3F800000u) return 2;
        if (v > 1u) return 0;
    }
    return 1;
}
__device__ __forceinline__ bool read_mask(const unsigned char* m, int i, int mode) {
    if (mode == 0) return m[i] != 0;
    if (mode == 1) return ((const int*)m)[i] != 0;
    return ((const float*)m)[i] != 0.0f;
}

// ---------------------------------------------------------------------------
// Kernel 1: scores -> bitonic top-k -> gather to fp16 scratch
// ---------------------------------------------------------------------------
__global__ __launch_bounds__(256) void select_gather_kernel(
    const float* __restrict__ cand, const float* __restrict__ ctxt,
    const unsigned char* __restrict__ mcand, const unsigned char* __restrict__ mctxt,
    const float* __restrict__ W, const float* __restrict__ bptr)
{
    __shared__ __align__(16) float Ws[DD];
    __shared__ unsigned long long keys[256];
    __shared__ int s_count;

    int tid = threadIdx.x;
    bool isCand = (blockIdx.x < BB*NQ);
    int row = isCand ? blockIdx.x : (blockIdx.x - BB*NQ);
    int L = isCand ? LQ : LK;
    int k = L >> 1;
    const float* rep = isCand ? (cand + (size_t)row * LQ * DD)
                              : (ctxt + (size_t)row * LK * DD);
    const unsigned char* mbase = isCand ? mcand : mctxt;
    int mmode = mask_mode(mbase);
    int moff  = row * L;

    if (tid < DD) Ws[tid] = W[tid];
    if (tid == 0) s_count = 0;
    __syncthreads();

    float bb = bptr[0];
    int wid = tid >> 5, lane = tid & 31;

    for (int t = wid; t < L; t += 8) {
        float4 v  = ((const float4*)(rep + t * DD))[lane];
        float4 w4 = ((const float4*)Ws)[lane];
        float acc = v.x*w4.x + v.y*w4.y + v.z*w4.z + v.w*w4.w;
        #pragma unroll
        for (int off = 16; off; off >>= 1) acc += __shfl_xor_sync(0xffffffffu, acc, off);
        if (lane == 0) {
            float s = read_mask(mbase, moff + t, mmode) ? (acc + bb) : NEGV;
            keys[t] = ((unsigned long long)fkey(s) << 32) | (unsigned int)(~t);
        }
    }
    __syncthreads();

    for (int size = 2; size <= L; size <<= 1) {
        for (int stride = size >> 1; stride > 0; stride >>= 1) {
            if (tid < L) {
                int j = tid ^ stride;
                if (j > tid) {
                    bool descend = ((tid & size) == 0);
                    unsigned long long a = keys[tid], c = keys[j];
                    if (descend ? (a < c) : (a > c)) { keys[tid] = c; keys[j] = a; }
                }
            }
            __syncthreads();
        }
    }

    if (isCand) {
        int cnt = 0;
        for (int j = tid; j < k; j += 256) {
            int t = (int)(~(unsigned int)keys[j]);
            if (read_mask(mbase, moff + t, mmode)) cnt++;
        }
        if (cnt) atomicAdd(&s_count, cnt);
        __syncthreads();
        if (tid == 0) g_candValid[row] = s_count;
        __half2* dst = (__half2*)(g_candSel + (size_t)row * KQ * DD);
        for (int e = tid; e < KQ * (DD/2); e += 256) {
            int j = e >> 6, d = e & 63;
            int t = (int)(~(unsigned int)keys[j]);
            float2 v = ((const float2*)(rep + t * DD))[d];
            dst[e] = __floats2half2_rn(v.x, v.y);
        }
    } else {
        for (int j = tid; j < k; j += 256) {
            int t = (int)(~(unsigned int)keys[j]);
            g_ctxtMask[row * KK + j] = read_mask(mbase, moff + t, mmode) ? 1.0f : 0.0f;
        }
        __half2* dst = (__half2*)(g_ctxtSel + (size_t)row * KK * DD);
        for (int e = tid; e < KK * (DD/2); e += 256) {
            int j = e >> 6, d = e & 63;
            int t = (int)(~(unsigned int)keys[j]);
            float2 v = ((const float2*)(rep + t * DD))[d];
            dst[e] = __floats2half2_rn(v.x, v.y);
        }
    }
}

// ---------------------------------------------------------------------------
// Kernel 2: one block per (bq, kk). cp.async staging, 32x32 warp tiles,
// 1-deep fragment pipeline, colmax + masked mean epilogue.
// ---------------------------------------------------------------------------
__device__ __forceinline__ void atomicMaxF(float* addr, float v) {
    if (v >= 0.f) atomicMax((int*)addr, __float_as_int(v));
    else          atomicMin((unsigned int*)addr, __float_as_uint(v));
}

__device__ __forceinline__ void ldsm_x4(unsigned int* r, unsigned int saddr) {
    asm volatile("ldmatrix.sync.aligned.m8n8.x4.shared.b16 {%0,%1,%2,%3}, [%4];"
                 : "=r"(r[0]), "=r"(r[1]), "=r"(r[2]), "=r"(r[3]) : "r"(saddr));
}
__device__ __forceinline__ void cp16(unsigned int dst, const void* src) {
    asm volatile("cp.async.cg.shared.global [%0], [%1], 16;\n" :: "r"(dst), "l"(src));
}
__device__ __forceinline__ void mma16816(float* C, const unsigned int* A,
                                         unsigned int b0, unsigned int b1) {
    asm volatile(
        "mma.sync.aligned.m16n8k16.row.col.f32.f16.f16.f32 "
        "{%0,%1,%2,%3}, {%4,%5,%6,%7}, {%8,%9}, {%0,%1,%2,%3};\n"
        : "+f"(C[0]), "+f"(C[1]), "+f"(C[2]), "+f"(C[3])
        : "r"(A[0]), "r"(A[1]), "r"(A[2]), "r"(A[3]), "r"(b0), "r"(b1));
}

__global__ __launch_bounds__(256, 3) void gemm_max_mean_kernel(float* __restrict__ out)
{
    extern __shared__ __align__(16) unsigned char smraw[];
    __half* As  = (__half*)smraw;                       // 64 x PADD
    __half* Bsh = (__half*)smraw + 64 * PADD;           // 128 x PADD
    float*  colmax = (float*)((__half*)smraw + (64 + 128) * PADD);  // 128
    __shared__ float sAccV, sAccM;

    int tid  = threadIdx.x;
    int lane = tid & 31, wid = tid >> 5;
    int wm = wid & 1;             // 0..1 : rows [wm*32, +32)
    int wn = wid >> 1;            // 0..3 : cols [wn*32, +32)
    int blk = blockIdx.x;
    int bq = blk >> 4;            // NK = 16
    int kk = blk & 15;
    int b  = bq >> 5;             // NQ = 32
    int g  = lane >> 2;
    int cpair = (lane & 3) * 2;

    // Stage A (64x128) and B (128x128) via cp.async (16B each)
    {
        const __half* Ag = g_candSel + (size_t)bq * KQ * DD;
        unsigned int AsAddr = (unsigned int)__cvta_generic_to_shared(As);
        for (int i = tid; i < 64 * 16; i += 256) {
            int r = i >> 4, seg = i & 15;
            cp16(AsAddr + (r * PADD + seg * 8) * 2, &Ag[r * DD + seg * 8]);
        }
        const __half* Bg = g_ctxtSel + ((size_t)(b * NK + kk)) * KK * DD;
        unsigned int BsAddr = (unsigned int)__cvta_generic_to_shared(Bsh);
        for (int i = tid; i < 128 * 16; i += 256) {
            int r = i >> 4, seg = i & 15;
            cp16(BsAddr + (r * PADD + seg * 8) * 2, &Bg[r * DD + seg * 8]);
        }
        asm volatile("cp.async.commit_group;\n");
    }
    if (tid < 128) colmax[tid] = NEGV;
    if (tid == 0) { sAccV = 0.f; sAccM = 0.f; }
    int nvalid = g_candValid[bq];
    asm volatile("cp.async.wait_group 0;\n");
    __syncthreads();

    // ldmatrix lane addressing
    int t8   = lane >> 3;
    int rsub = lane & 7;
    unsigned int aAddr = (unsigned int)__cvta_generic_to_shared(
        &As[(wm * 32 + (t8 & 1) * 8 + rsub) * PADD + (t8 >> 1) * 8]);
    unsigned int bAddr = (unsigned int)__cvta_generic_to_shared(
        &Bsh[(wn * 32 + (t8 & 1) * 8 + rsub) * PADD + (t8 >> 1) * 8]);
    const unsigned int mtStep = 16 * PADD * 2;   // +16 rows in bytes

    float C[2][4][4];
    #pragma unroll
    for (int mt = 0; mt < 2; mt++)
        #pragma unroll
        for (int np = 0; np < 4; np++)
            #pragma unroll
            for (int j = 0; j < 4; j++) C[mt][np][j] = 0.f;

    // fragment double buffers
    unsigned int aF[2][2][4], bF[2][2][4];
    ldsm_x4(aF[0][0], aAddr);
    ldsm_x4(aF[0][1], aAddr + mtStep);
    ldsm_x4(bF[0][0], bAddr);
    ldsm_x4(bF[0][1], bAddr + mtStep);

    #pragma unroll
    for (int ks = 0; ks < 8; ks++) {
        int cur = ks & 1, nxt = cur ^ 1;
        if (ks < 7) {
            unsigned int off = (ks + 1) * 32;   // +16 halfs in bytes
            ldsm_x4(aF[nxt][0], aAddr + off);
            ldsm_x4(aF[nxt][1], aAddr + mtStep + off);
            ldsm_x4(bF[nxt][0], bAddr + off);
            ldsm_x4(bF[nxt][1], bAddr + mtStep + off);
        }
        #pragma unroll
        for (int mt = 0; mt < 2; mt++) {
            #pragma unroll
            for (int p = 0; p < 2; p++) {
                // n-frag 2p   : b0=q0, b1=q2 ; n-frag 2p+1 : b0=q1, b1=q3
                mma16816(C[mt][2*p],   aF[cur][mt], bF[cur][p][0], bF[cur][p][2]);
                mma16816(C[mt][2*p+1], aF[cur][mt], bF[cur][p][1], bF[cur][p][3]);
            }
        }
    }

    // masked column max (rows >= nvalid excluded)
    #pragma unroll
    for (int mt = 0; mt < 2; mt++) {
        int r0 = wm * 32 + mt * 16 + g;
        bool ok0 = (r0 < nvalid), ok1 = (r0 + 8 < nvalid);
        #pragma unroll
        for (int np = 0; np < 4; np++) {
            float m0 = fmaxf(ok0 ? C[mt][np][0] : NEGV, ok1 ? C[mt][np][2] : NEGV);
            float m1 = fmaxf(ok0 ? C[mt][np][1] : NEGV, ok1 ? C[mt][np][3] : NEGV);
            #pragma unroll
            for (int off = 4; off < 32; off <<= 1) {
                m0 = fmaxf(m0, __shfl_xor_sync(0xffffffffu, m0, off));
                m1 = fmaxf(m1, __shfl_xor_sync(0xffffffffu, m1, off));
            }
            if (lane < 4) {
                int col = wn * 32 + np * 8 + cpair;
                atomicMaxF(&colmax[col],     m0);
                atomicMaxF(&colmax[col + 1], m1);
            }
        }
    }
    __syncthreads();

    // masked mean over 128 ctxt tokens
    if (tid < 128) {
        float m = g_ctxtMask[(b * NK + kk) * KK + tid];
        float v = colmax[tid] * m;
        #pragma unroll
        for (int off = 16; off; off >>= 1) {
            v += __shfl_xor_sync(0xffffffffu, v, off);
            m += __shfl_xor_sync(0xffffffffu, m, off);
        }
        if (lane == 0) { atomicAdd(&sAccV, v); atomicAdd(&sAccM, m); }
    }
    __syncthreads();
    if (tid == 0) out[bq * NK + kk] = sAccV / sAccM;
}

// ---------------------------------------------------------------------------
extern "C" void kernel_launch(void* const* d_in, const int* in_sizes, int n_in,
                              void* d_out, int out_size)
{
    const float*         cand  = (const float*)d_in[0];
    const float*         ctxt  = (const float*)d_in[1];
    const unsigned char* mcand = (const unsigned char*)d_in[2];
    const unsigned char* mctxt = (const unsigned char*)d_in[3];
    const float*         W     = (const float*)d_in[4];
    const float*         bptr  = (const float*)d_in[5];
    float* out = (float*)d_out;

    cudaFuncSetAttribute(gemm_max_mean_kernel,
                         cudaFuncAttributeMaxDynamicSharedMemorySize, SMEM_K2);

    select_gather_kernel<<<BB*NQ + BB*NK, 256>>>(cand, ctxt, mcand, mctxt, W, bptr);
    gemm_max_mean_kernel<<<BB*NQ*NK, 256, SMEM_K2>>>(out);
}

// round 8
// speedup vs baseline: 1.9694x; 1.1891x over previous
#include <cuda_runtime.h>
#include <cuda_fp16.h>
#include <cstdint>

#define BB 8
#define NQ 32
#define LQ 128
#define NK 16
#define LK 256
#define DD 128
#define KQ 64
#define KK 128
#define NEGV -99999.0f
#define PADD 136 // halfs per smem row (16B pad per 256B row -> conflict-free ldmatrix)

// K2 smem: A(ctxt) 128 x PADD + B(cand) 64 x PADD halfs + rowmax[128] floats
#define SMEM_K2 ((128 + 64) * PADD * 2 + 128 * 4)

__device__ __align__(16) __half g_candSel[BB*NQ*KQ*DD];   // 4 MB [token][dim]
__device__ __align__(16) __half g_ctxtSel[BB*NK*KK*DD];   // 4 MB [token][dim]
__device__ int   g_candValid[BB*NQ];
__device__ float g_ctxtMask[BB*NK*KK];

__device__ __forceinline__ unsigned int fkey(float f) {
    unsigned int u = __float_as_uint(f);
    return (u & 0x80000000u) ? ~u : (u | 0x80000000u);
}
__device__ __forceinline__ int mask_mode(const unsigned char* m) {
    const unsigned int* w = (const unsigned int*)m;
    #pragma unroll
    for (int i = 0; i < 4; i++) {
        unsigned int v = w[i];
        if (v == 0x3F800000u) return 2;
        if (v > 1u) return 0;
    }
    return 1;
}
__device__ __forceinline__ bool read_mask(const unsigned char* m, int i, int mode) {
    if (mode == 0) return m[i] != 0;
    if (mode == 1) return ((const int*)m)[i] != 0;
    return ((const float*)m)[i] != 0.0f;
}

// ---------------------------------------------------------------------------
// Kernel 1: scores -> bitonic top-k -> gather to fp16 scratch (512 threads)
// ---------------------------------------------------------------------------
__global__ __launch_bounds__(512) void select_gather_kernel(
    const float* __restrict__ cand, const float* __restrict__ ctxt,
    const unsigned char* __restrict__ mcand, const unsigned char* __restrict__ mctxt,
    const float* __restrict__ W, const float* __restrict__ bptr)
{
    __shared__ __align__(16) float Ws[DD];
    __shared__ unsigned long long keys[256];
    __shared__ int s_count;

    int tid = threadIdx.x;
    bool isCand = (blockIdx.x < BB*NQ);
    int row = isCand ? blockIdx.x : (blockIdx.x - BB*NQ);
    int L = isCand ? LQ : LK;
    int k = L >> 1;
    const float* rep = isCand ? (cand + (size_t)row * LQ * DD)
                              : (ctxt + (size_t)row * LK * DD);
    const unsigned char* mbase = isCand ? mcand : mctxt;
    int mmode = mask_mode(mbase);
    int moff  = row * L;

    if (tid < DD) Ws[tid] = W[tid];
    if (tid == 0) s_count = 0;
    __syncthreads();

    float bb = bptr[0];
    int wid = tid >> 5, lane = tid & 31;

    for (int t = wid; t < L; t += 16) {
        float4 v  = ((const float4*)(rep + t * DD))[lane];
        float4 w4 = ((const float4*)Ws)[lane];
        float acc = v.x*w4.x + v.y*w4.y + v.z*w4.z + v.w*w4.w;
        #pragma unroll
        for (int off = 16; off; off >>= 1) acc += __shfl_xor_sync(0xffffffffu, acc, off);
        if (lane == 0) {
            float s = read_mask(mbase, moff + t, mmode) ? (acc + bb) : NEGV;
            keys[t] = ((unsigned long long)fkey(s) << 32) | (unsigned int)(~t);
        }
    }
    __syncthreads();

    for (int size = 2; size <= L; size <<= 1) {
        for (int stride = size >> 1; stride > 0; stride >>= 1) {
            if (tid < L) {
                int j = tid ^ stride;
                if (j > tid) {
                    bool descend = ((tid & size) == 0);
                    unsigned long long a = keys[tid], c = keys[j];
                    if (descend ? (a < c) : (a > c)) { keys[tid] = c; keys[j] = a; }
                }
            }
            __syncthreads();
        }
    }

    if (isCand) {
        int cnt = 0;
        for (int j = tid; j < k; j += 512) {
            int t = (int)(~(unsigned int)keys[j]);
            if (read_mask(mbase, moff + t, mmode)) cnt++;
        }
        if (cnt) atomicAdd(&s_count, cnt);
        __syncthreads();
        if (tid == 0) g_candValid[row] = s_count;
        __half2* dst = (__half2*)(g_candSel + (size_t)row * KQ * DD);
        for (int e = tid; e < KQ * (DD/2); e += 512) {
            int j = e >> 6, d = e & 63;
            int t = (int)(~(unsigned int)keys[j]);
            float2 v = ((const float2*)(rep + t * DD))[d];
            dst[e] = __floats2half2_rn(v.x, v.y);
        }
    } else {
        for (int j = tid; j < k; j += 512) {
            int t = (int)(~(unsigned int)keys[j]);
            g_ctxtMask[row * KK + j] = read_mask(mbase, moff + t, mmode) ? 1.0f : 0.0f;
        }
        __half2* dst = (__half2*)(g_ctxtSel + (size_t)row * KK * DD);
        for (int e = tid; e < KK * (DD/2); e += 512) {
            int j = e >> 6, d = e & 63;
            int t = (int)(~(unsigned int)keys[j]);
            float2 v = ((const float2*)(rep + t * DD))[d];
            dst[e] = __floats2half2_rn(v.x, v.y);
        }
    }
}

// ---------------------------------------------------------------------------
// Kernel 2: one block per (bq, kk). TRANSPOSED: D[128 ctxt, 64 cand].
// MaxSim over cand = column max -> register max + quad shuffle + 1 atomic/row.
// Warps: wm=wid>>1 (0..3) ctxt rows [wm*32,+32); wn=wid&1 cand cols [wn*32,+32)
// ---------------------------------------------------------------------------
__device__ __forceinline__ void atomicMaxF(float* addr, float v) {
    if (v >= 0.f) atomicMax((int*)addr, __float_as_int(v));
    else          atomicMin((unsigned int*)addr, __float_as_uint(v));
}
__device__ __forceinline__ void ldsm_x4(unsigned int* r, unsigned int saddr) {
    asm volatile("ldmatrix.sync.aligned.m8n8.x4.shared.b16 {%0,%1,%2,%3}, [%4];"
                 : "=r"(r[0]), "=r"(r[1]), "=r"(r[2]), "=r"(r[3]) : "r"(saddr));
}
__device__ __forceinline__ void cp16(unsigned int dst, const void* src) {
    asm volatile("cp.async.cg.shared.global [%0], [%1], 16;\n" :: "r"(dst), "l"(src));
}
__device__ __forceinline__ void mma16816(float* C, const unsigned int* A,
                                         unsigned int b0, unsigned int b1) {
    asm volatile(
        "mma.sync.aligned.m16n8k16.row.col.f32.f16.f16.f32 "
        "{%0,%1,%2,%3}, {%4,%5,%6,%7}, {%8,%9}, {%0,%1,%2,%3};\n"
        : "+f"(C[0]), "+f"(C[1]), "+f"(C[2]), "+f"(C[3])
        : "r"(A[0]), "r"(A[1]), "r"(A[2]), "r"(A[3]), "r"(b0), "r"(b1));
}

__global__ __launch_bounds__(256, 3) void gemm_max_mean_kernel(float* __restrict__ out)
{
    extern __shared__ __align__(16) unsigned char smraw[];
    __half* As  = (__half*)smraw;                       // ctxt: 128 x PADD
    __half* Bsh = (__half*)smraw + 128 * PADD;          // cand: 64 x PADD
    float*  rowmax = (float*)((__half*)smraw + (128 + 64) * PADD);  // 128
    __shared__ float sAccV, sAccM;

    int tid  = threadIdx.x;
    int lane = tid & 31, wid = tid >> 5;
    int wm = wid >> 1;            // 0..3 : ctxt rows [wm*32, +32)
    int wn = wid & 1;             // 0..1 : cand cols [wn*32, +32)
    int blk = blockIdx.x;
    int bq = blk >> 4;            // NK = 16
    int kk = blk & 15;
    int b  = bq >> 5;             // NQ = 32
    int g  = lane >> 2;
    int cpair = (lane & 3) * 2;

    // Stage A = ctxt (128x128), B = cand (64x128) via cp.async
    {
        const __half* Ag = g_ctxtSel + ((size_t)(b * NK + kk)) * KK * DD;
        unsigned int AsAddr = (unsigned int)__cvta_generic_to_shared(As);
        for (int i = tid; i < 128 * 16; i += 256) {
            int r = i >> 4, seg = i & 15;
            cp16(AsAddr + (r * PADD + seg * 8) * 2, &Ag[r * DD + seg * 8]);
        }
        const __half* Bg = g_candSel + (size_t)bq * KQ * DD;
        unsigned int BsAddr = (unsigned int)__cvta_generic_to_shared(Bsh);
        for (int i = tid; i < 64 * 16; i += 256) {
            int r = i >> 4, seg = i & 15;
            cp16(BsAddr + (r * PADD + seg * 8) * 2, &Bg[r * DD + seg * 8]);
        }
        asm volatile("cp.async.commit_group;\n");
    }
    if (tid < 128) rowmax[tid] = NEGV;
    if (tid == 0) { sAccV = 0.f; sAccM = 0.f; }
    int nvalid = g_candValid[bq];
    asm volatile("cp.async.wait_group 0;\n");
    __syncthreads();

    // ldmatrix lane addressing
    int t8   = lane >> 3;
    int rsub = lane & 7;
    unsigned int aAddr = (unsigned int)__cvta_generic_to_shared(
        &As[(wm * 32 + (t8 & 1) * 8 + rsub) * PADD + (t8 >> 1) * 8]);
    unsigned int bAddr = (unsigned int)__cvta_generic_to_shared(
        &Bsh[(wn * 32 + (t8 & 1) * 8 + rsub) * PADD + (t8 >> 1) * 8]);
    const unsigned int mtStep = 16 * PADD * 2;   // +16 rows in bytes

    float C[2][4][4];
    #pragma unroll
    for (int mt = 0; mt < 2; mt++)
        #pragma unroll
        for (int np = 0; np < 4; np++)
            #pragma unroll
            for (int j = 0; j < 4; j++) C[mt][np][j] = 0.f;

    unsigned int aF[2][2][4], bF[2][2][4];
    ldsm_x4(aF[0][0], aAddr);
    ldsm_x4(aF[0][1], aAddr + mtStep);
    ldsm_x4(bF[0][0], bAddr);
    ldsm_x4(bF[0][1], bAddr + mtStep);

    #pragma unroll
    for (int ks = 0; ks < 8; ks++) {
        int cur = ks & 1, nxt = cur ^ 1;
        if (ks < 7) {
            unsigned int off = (ks + 1) * 32;
            ldsm_x4(aF[nxt][0], aAddr + off);
            ldsm_x4(aF[nxt][1], aAddr + mtStep + off);
            ldsm_x4(bF[nxt][0], bAddr + off);
            ldsm_x4(bF[nxt][1], bAddr + mtStep + off);
        }
        #pragma unroll
        for (int mt = 0; mt < 2; mt++) {
            #pragma unroll
            for (int p = 0; p < 2; p++) {
                mma16816(C[mt][2*p],   aF[cur][mt], bF[cur][p][0], bF[cur][p][2]);
                mma16816(C[mt][2*p+1], aF[cur][mt], bF[cur][p][1], bF[cur][p][3]);
            }
        }
    }

    // register column-masked row max (cand cols >= nvalid excluded)
    #pragma unroll
    for (int mt = 0; mt < 2; mt++) {
        float m0 = NEGV, m1 = NEGV;
        #pragma unroll
        for (int np = 0; np < 4; np++) {
            int col = wn * 32 + np * 8 + cpair;
            bool v0 = (col < nvalid), v1 = (col + 1 < nvalid);
            m0 = fmaxf(m0, fmaxf(v0 ? C[mt][np][0] : NEGV, v1 ? C[mt][np][1] : NEGV));
            m1 = fmaxf(m1, fmaxf(v0 ? C[mt][np][2] : NEGV, v1 ? C[mt][np][3] : NEGV));
        }
        #pragma unroll
        for (int off = 1; off < 4; off <<= 1) {
            m0 = fmaxf(m0, __shfl_xor_sync(0xffffffffu, m0, off));
            m1 = fmaxf(m1, __shfl_xor_sync(0xffffffffu, m1, off));
        }
        if ((lane & 3) == 0) {
            int r = wm * 32 + mt * 16 + g;
            atomicMaxF(&rowmax[r],     m0);
            atomicMaxF(&rowmax[r + 8], m1);
        }
    }
    __syncthreads();

    // masked mean over 128 ctxt tokens (rows)
    if (tid < 128) {
        float m = g_ctxtMask[(b * NK + kk) * KK + tid];
        float v = rowmax[tid] * m;
        #pragma unroll
        for (int off = 16; off; off >>= 1) {
            v += __shfl_xor_sync(0xffffffffu, v, off);
            m += __shfl_xor_sync(0xffffffffu, m, off);
        }
        if (lane == 0) { atomicAdd(&sAccV, v); atomicAdd(&sAccM, m); }
    }
    __syncthreads();
    if (tid == 0) out[bq * NK + kk] = sAccV / sAccM;
}

// ---------------------------------------------------------------------------
extern "C" void kernel_launch(void* const* d_in, const int* in_sizes, int n_in,
                              void* d_out, int out_size)
{
    const float*         cand  = (const float*)d_in[0];
    const float*         ctxt  = (const float*)d_in[1];
    const unsigned char* mcand = (const unsigned char*)d_in[2];
    const unsigned char* mctxt = (const unsigned char*)d_in[3];
    const float*         W     = (const float*)d_in[4];
    const float*         bptr  = (const float*)d_in[5];
    float* out = (float*)d_out;

    cudaFuncSetAttribute(gemm_max_mean_kernel,
                         cudaFuncAttributeMaxDynamicSharedMemorySize, SMEM_K2);

    select_gather_kernel<<<BB*NQ + BB*NK, 512>>>(cand, ctxt, mcand, mctxt, W, bptr);
    gemm_max_mean_kernel<<<BB*NQ*NK, 256, SMEM_K2>>>(out);
}